// round 17
// baseline (speedup 1.0000x reference)
#include <cuda_runtime.h>

#define K2T  49
#define NH   3
#define DIMC 96
#define NT   512

typedef unsigned long long u64;

// ---- global scratch (prep) ----
__device__ float gGwT[DIMC * DIMC];           // gGwT[he][c] = Gw[c*96+he]
__device__ float gBias[NH * K2T * K2T];       // gBias[h][i*49+j] = rpb[rp[ij]*3+h]

// ---- shared memory layout (floats) ----
#define XT_STR  60
#define XT_OFF  0                               // xT[96][60], cols 49..55 zero
#define P_OFF   (XT_OFF + 96 * XT_STR)          // P[288][60]: Q 0..95 (scaled), K 96..191, Y^T 192..287
#define P_STR   60
#define S_OFF   (P_OFF + 288 * P_STR)           // S[150][60]
#define S_STR   60
#define VT_OFF  (S_OFF + 150 * S_STR)           // VT[96][60]  VT[he][i]
#define VT_STR  60
#define BOTT_OFF (VT_OFF + 96 * VT_STR)
#define SMEM_FLOATS (BOTT_OFF + 64)             // ~151.5 KB

__device__ __forceinline__ float fcomp(float4 v, int k) {
    return k == 0 ? v.x : (k == 1 ? v.y : (k == 2 ? v.z : v.w));
}
// packed 2xfp32 fma on native 64-bit regs (no pack/unpack movs on the chain)
__device__ __forceinline__ u64 ffma2(u64 a, u64 b, u64 c) {
    u64 d;
    asm("fma.rn.f32x2 %0, %1, %2, %3;" : "=l"(d) : "l"(a), "l"(b), "l"(c));
    return d;
}
__device__ __forceinline__ u64 bcast2(float w) {
    u64 r;
    asm("mov.b64 %0, {%1,%1};" : "=l"(r) : "f"(w));
    return r;
}
__device__ __forceinline__ u64 pk2(float x, float y) {
    u64 r;
    asm("mov.b64 %0, {%1,%2};" : "=l"(r) : "f"(x), "f"(y));
    return r;
}
__device__ __forceinline__ float2 unpk(u64 a) {
    float2 r;
    asm("mov.b64 {%0,%1}, %2;" : "=f"(r.x), "=f"(r.y) : "l"(a));
    return r;
}

// ================= prep =================
__global__ void prep_kernel(const float* __restrict__ Gw,
                            const float* __restrict__ rpb,
                            const int*   __restrict__ rp)
{
    int t = blockIdx.x * blockDim.x + threadIdx.x;
    if (t < DIMC * DIMC) {
        int c = t / DIMC, he = t - c * DIMC;
        gGwT[he * DIMC + c] = Gw[t];
    }
    if (t < NH * K2T * K2T) {
        int h = t / (K2T * K2T), ij = t - h * (K2T * K2T);
        gBias[t] = rpb[rp[ij] * NH + h];
    }
}

// ================= monolithic per-window kernel =================
__global__ __launch_bounds__(NT, 1)
void gwa_kernel(const float* __restrict__ x,    const float* __restrict__ mask,
                const float* __restrict__ qk_w, const float* __restrict__ qk_b,
                const float* __restrict__ botw, const float* __restrict__ botb,
                const float* __restrict__ Bw,   const float* __restrict__ pw,
                const float* __restrict__ pb,
                float* __restrict__ out, int nW)
{
    extern __shared__ float sm[];
    float* xT   = sm + XT_OFF;
    float* P    = sm + P_OFF;
    float* S    = sm + S_OFF;
    float* VT   = sm + VT_OFF;
    float* bott = sm + BOTT_OFF;

    const int b   = blockIdx.x;
    const int tid = threadIdx.x;
    const float* xg = x + (size_t)b * (K2T * DIMC);
    const float SCALE = 0.17677669529663687f;   // 32^-0.5

    // ---------------- Phase 1: stage xT transposed + pads ----------------
    for (int i = tid; i < K2T * DIMC; i += NT) {
        int j = i / DIMC, c = i - j * DIMC;
        xT[c * XT_STR + j] = xg[i];
    }
    for (int i = tid; i < DIMC * 7; i += NT) {   // zero xT cols 49..55
        int c = i / 7, j = K2T + (i % 7);
        xT[c * XT_STR + j] = 0.f;
    }
    __syncthreads();

    // ---------------- Phase 2: projection (252 tiles) + bott (idle threads) ----------------
    if (tid < 252) {
        const int rt = tid / 7;                  // 0..35
        const int jt = tid - rt * 7;             // 0..6
        const int r0 = rt * 8;
        const int j0 = jt * 8;
        const bool isQK = (r0 < 192);
        const float* wbase = isQK ? (qk_w + r0 * 96) : (gGwT + (r0 - 192) * 96);

        u64 acc[8][4];                           // 8 rows x 4 j-pairs
        #pragma unroll
        for (int a = 0; a < 8; a++) {
            float bv = isQK ? qk_b[r0 + a] : 0.f;
            u64 bp = bcast2(bv);
            #pragma unroll
            for (int p = 0; p < 4; p++) acc[a][p] = bp;
        }

        for (int c0 = 0; c0 < DIMC; c0 += 4) {
            u64 xq[4][4];                        // [cc][j-pair]
            #pragma unroll
            for (int cc = 0; cc < 4; cc++) {
                ulonglong2 xa = *(const ulonglong2*)&xT[(c0 + cc) * XT_STR + j0];
                ulonglong2 xb = *(const ulonglong2*)&xT[(c0 + cc) * XT_STR + j0 + 4];
                xq[cc][0] = xa.x; xq[cc][1] = xa.y;
                xq[cc][2] = xb.x; xq[cc][3] = xb.y;
            }
            #pragma unroll
            for (int a = 0; a < 8; a++) {
                float4 wv = *(const float4*)&wbase[a * 96 + c0];
                #pragma unroll
                for (int cc = 0; cc < 4; cc++) {
                    u64 w2 = bcast2(fcomp(wv, cc));
                    #pragma unroll
                    for (int p = 0; p < 4; p++)
                        acc[a][p] = ffma2(w2, xq[cc][p], acc[a][p]);
                }
            }
        }

        const float s = (r0 < 96) ? SCALE : 1.f;
        #pragma unroll
        for (int a = 0; a < 8; a++) {
            float2 p0 = unpk(acc[a][0]), p1 = unpk(acc[a][1]);
            float2 p2 = unpk(acc[a][2]), p3 = unpk(acc[a][3]);
            float4 o0 = make_float4(p0.x * s, p0.y * s, p1.x * s, p1.y * s);
            float4 o1 = make_float4(p2.x * s, p2.y * s, p3.x * s, p3.y * s);
            *(float4*)&P[(r0 + a) * P_STR + j0]     = o0;
            *(float4*)&P[(r0 + a) * P_STR + j0 + 4] = o1;
        }
    } else if (tid >= 256 && tid < 308) {
        // bott[j] from staged xT (overlaps projection; off critical path)
        int j = tid - 256;
        float acc = botb[0];
        #pragma unroll 4
        for (int c = 0; c < DIMC; c++) acc = fmaf(xT[c * XT_STR + j], botw[c], acc);
        bott[j] = acc;
    }
    __syncthreads();

    // ---------------- Phase 3: logits 4i x 8j tiles (273) + bias/mask ----------------
    const float* maskb = mask + (size_t)(b % nW) * (K2T * K2T);
    if (tid < 273) {
        const int h   = tid / 91;
        const int rem = tid - h * 91;
        const int it  = rem / 7;
        const int jt  = rem - it * 7;
        const int i0  = it * 4;
        const int j0  = jt * 8;
        const float* qb = P + (h * 32) * P_STR + i0;
        const float* kb = P + (96 + h * 32) * P_STR + j0;

        u64 acc[4][4];
        #pragma unroll
        for (int ii = 0; ii < 4; ii++)
            #pragma unroll
            for (int jp = 0; jp < 4; jp++) acc[ii][jp] = 0ULL;

        #pragma unroll 2
        for (int e = 0; e < 32; e++) {
            float4 qv  = *(const float4*)&qb[e * P_STR];
            ulonglong2 ka = *(const ulonglong2*)&kb[e * P_STR];
            ulonglong2 kbv = *(const ulonglong2*)&kb[e * P_STR + 4];
            u64 kp[4] = { ka.x, ka.y, kbv.x, kbv.y };
            #pragma unroll
            for (int ii = 0; ii < 4; ii++) {
                u64 q2 = bcast2(fcomp(qv, ii));
                #pragma unroll
                for (int jp = 0; jp < 4; jp++)
                    acc[ii][jp] = ffma2(q2, kp[jp], acc[ii][jp]);
            }
        }

        const float* biash = gBias + h * (K2T * K2T);
        #pragma unroll
        for (int ii = 0; ii < 4; ii++) {
            int i = i0 + ii;
            if (i < K2T) {
                float* srow = S + (h * K2T + i) * S_STR;
                float2 u0 = unpk(acc[ii][0]), u1 = unpk(acc[ii][1]);
                float2 u2 = unpk(acc[ii][2]), u3 = unpk(acc[ii][3]);
                float av[8] = { u0.x, u0.y, u1.x, u1.y, u2.x, u2.y, u3.x, u3.y };
                #pragma unroll
                for (int jj = 0; jj < 8; jj++) {
                    int j = j0 + jj;
                    float v = av[jj];
                    if (j < K2T) {
                        int idx = i * K2T + j;
                        v += biash[idx] + maskb[idx];
                    }
                    srow[j] = v;   // pad cols garbage; nulled by zero Y pads in P5
                }
            }
        }
    } else if (tid >= 320 && tid < 320 + 45) {   // zero S guard rows 147..149
        int t = tid - 320;
        int rr = 147 + t / 15, f = (t % 15) * 4;
        *(float4*)&S[rr * S_STR + f] = make_float4(0.f, 0.f, 0.f, 0.f);
    }
    __syncthreads();

    // ---------------- Phase 4: softmax (no max-shift; logits bounded), 2 rows/warp-iter ----------------
    {
        int warp = tid >> 5, lane = tid & 31;
        for (int row = warp; row < NH * K2T; row += 32) {
            int rowb = row + 16;
            bool hb = rowb < NH * K2T;
            float* sa = S + row * S_STR;
            float* sb = S + rowb * S_STR;
            float a0 = sa[lane];
            float a1 = (lane < 17) ? sa[32 + lane] : 0.f;
            float b0 = hb ? sb[lane] : 0.f;
            float b1 = (hb && lane < 17) ? sb[32 + lane] : 0.f;
            float ea0 = __expf(a0);
            float ea1 = (lane < 17) ? __expf(a1) : 0.f;
            float eb0 = __expf(b0);
            float eb1 = (hb && lane < 17) ? __expf(b1) : 0.f;
            float sumA = ea0 + ea1;
            float sumB = hb ? (eb0 + eb1) : 1.f;
            #pragma unroll
            for (int o = 16; o; o >>= 1) {
                sumA += __shfl_xor_sync(~0u, sumA, o);
                sumB += __shfl_xor_sync(~0u, sumB, o);
            }
            float invA = __fdividef(1.f, sumA);
            float invB = __fdividef(1.f, sumB);
            sa[lane] = ea0 * invA;
            if (lane < 17) sa[32 + lane] = ea1 * invA;
            if (hb) {
                sb[lane] = eb0 * invB;
                if (lane < 17) sb[32 + lane] = eb1 * invB;
            }
        }
    }
    __syncthreads();

    // ---------------- Phase 5: VT = bott*(S@Y^T + Bw), 4i x 8e tiles (156) ----------------
    if (tid < 156) {
        const int h   = tid / 52;
        const int rem = tid - h * 52;
        const int et  = rem / 13;
        const int it  = rem - et * 13;
        const int i0  = it * 4;
        const int e0  = et * 8;
        const float* sbase = S + (h * K2T + i0) * S_STR;
        const float* ybase = P + (192 + h * 32 + e0) * P_STR;

        u64 acc[4][8];
        #pragma unroll
        for (int ii = 0; ii < 4; ii++)
            #pragma unroll
            for (int ee = 0; ee < 8; ee++) acc[ii][ee] = 0ULL;

        #pragma unroll 2
        for (int j0 = 0; j0 < 56; j0 += 4) {     // S/Y cols 49..55: garbage x exact-zero Y
            u64 sp[4][2], yp[8][2];
            #pragma unroll
            for (int ii = 0; ii < 4; ii++) {
                ulonglong2 sv = *(const ulonglong2*)&sbase[ii * S_STR + j0];
                sp[ii][0] = sv.x; sp[ii][1] = sv.y;
            }
            #pragma unroll
            for (int ee = 0; ee < 8; ee++) {
                ulonglong2 yv = *(const ulonglong2*)&ybase[ee * P_STR + j0];
                yp[ee][0] = yv.x; yp[ee][1] = yv.y;
            }
            #pragma unroll
            for (int ii = 0; ii < 4; ii++)
                #pragma unroll
                for (int ee = 0; ee < 8; ee++) {
                    acc[ii][ee] = ffma2(sp[ii][0], yp[ee][0], acc[ii][ee]);
                    acc[ii][ee] = ffma2(sp[ii][1], yp[ee][1], acc[ii][ee]);
                }
        }

        float bt[4];
        #pragma unroll
        for (int ii = 0; ii < 4; ii++) bt[ii] = bott[i0 + ii];
        #pragma unroll
        for (int ee = 0; ee < 8; ee++) {
            float bw = Bw[h * 32 + e0 + ee];
            float2 u0 = unpk(acc[0][ee]), u1 = unpk(acc[1][ee]);
            float2 u2 = unpk(acc[2][ee]), u3 = unpk(acc[3][ee]);
            float4 o = make_float4(bt[0] * (u0.x + u0.y + bw),
                                   bt[1] * (u1.x + u1.y + bw),
                                   bt[2] * (u2.x + u2.y + bw),
                                   bt[3] * (u3.x + u3.y + bw));
            *(float4*)&VT[(h * 32 + e0 + ee) * VT_STR + i0] = o;
        }
    }
    __syncthreads();

    // ---------------- Phase 6: out projection, 8i x 4d tiles (168) ----------------
    float* og = out + (size_t)b * (K2T * DIMC);
    if (tid < 168) {
        const int dt = tid / 7;                  // 0..23
        const int it = tid - dt * 7;             // 0..6
        const int d0 = dt * 4;
        const int i0 = it * 8;

        u64 acc[4][4];   // [i-pair 0..3 covering 8 i][d 0..3]
        #pragma unroll
        for (int dd = 0; dd < 4; dd++) {
            u64 bp = bcast2(pb[d0 + dd]);
            #pragma unroll
            for (int p = 0; p < 4; p++) acc[p][dd] = bp;
        }

        for (int c0 = 0; c0 < DIMC; c0 += 4) {
            u64 vq[4][4];                        // [cc][i-pair]
            #pragma unroll
            for (int cc = 0; cc < 4; cc++) {
                ulonglong2 va = *(const ulonglong2*)&VT[(c0 + cc) * VT_STR + i0];
                ulonglong2 vb = *(const ulonglong2*)&VT[(c0 + cc) * VT_STR + i0 + 4];
                vq[cc][0] = va.x; vq[cc][1] = va.y;
                vq[cc][2] = vb.x; vq[cc][3] = vb.y;
            }
            #pragma unroll
            for (int dd = 0; dd < 4; dd++) {
                float4 wv = *(const float4*)&pw[(d0 + dd) * 96 + c0];
                #pragma unroll
                for (int cc = 0; cc < 4; cc++) {
                    u64 w2 = bcast2(fcomp(wv, cc));
                    #pragma unroll
                    for (int p = 0; p < 4; p++)
                        acc[p][dd] = ffma2(w2, vq[cc][p], acc[p][dd]);
                }
            }
        }

        #pragma unroll
        for (int p = 0; p < 4; p++) {
            float2 u0 = unpk(acc[p][0]), u1 = unpk(acc[p][1]);
            float2 u2 = unpk(acc[p][2]), u3 = unpk(acc[p][3]);
            #pragma unroll
            for (int half = 0; half < 2; half++) {
                int i = i0 + p * 2 + half;
                if (i < K2T) {
                    float4 o = (half == 0)
                        ? make_float4(u0.x, u1.x, u2.x, u3.x)
                        : make_float4(u0.y, u1.y, u2.y, u3.y);
                    *(float4*)&og[i * DIMC + d0] = o;
                }
            }
        }
    }
}

extern "C" void kernel_launch(void* const* d_in, const int* in_sizes, int n_in,
                              void* d_out, int out_size) {
    const float* x    = (const float*)d_in[0];
    const float* mask = (const float*)d_in[1];
    const float* qk_w = (const float*)d_in[2];
    const float* qk_b = (const float*)d_in[3];
    const float* rpb  = (const float*)d_in[4];
    const float* botw = (const float*)d_in[5];
    const float* botb = (const float*)d_in[6];
    const float* Gw   = (const float*)d_in[7];
    const float* Bw   = (const float*)d_in[8];
    const float* pw   = (const float*)d_in[9];
    const float* pb   = (const float*)d_in[10];
    const int*   rp   = (const int*)d_in[11];

    const int BW = in_sizes[0] / (K2T * DIMC);   // 128
    const int nW = in_sizes[1] / (K2T * K2T);    // 64

    prep_kernel<<<(DIMC * DIMC + 255) / 256, 256>>>(Gw, rpb, rp);

    size_t smem = SMEM_FLOATS * sizeof(float);
    cudaFuncSetAttribute(gwa_kernel, cudaFuncAttributeMaxDynamicSharedMemorySize, (int)smem);
    gwa_kernel<<<BW, NT, smem>>>(x, mask, qk_w, qk_b, botw, botb,
                                 Bw, pw, pb, (float*)d_out, nW);
}